// round 1
// baseline (speedup 1.0000x reference)
#include <cuda_runtime.h>
#include <cstddef>

// ---------------------------------------------------------------------------
// InvariantReadout: 3-layer SiLU MLP + attention-softmax segment readout
//   h = silu(X@W1+b1); h = silu(h@W2+b2); x = h@W3+b3
//   logits = silu(X@aW1+ab1)@aW2 + ab2
//   per-segment softmax(logits) -> weighted segment_sum of x  -> (G, 256)
// ---------------------------------------------------------------------------

#define N_MAX 200000
#define DIM   256

// Scratch (allocation-free rule: __device__ globals)
__device__ float g_buf0[(size_t)N_MAX * DIM];
__device__ float g_buf1[(size_t)N_MAX * DIM];
__device__ float g_logits[N_MAX];

__device__ __forceinline__ float silu_f(float x) {
    return x / (1.0f + __expf(-x));
}

// ---------------------------------------------------------------------------
// GEMM: C(nRows x 256) = act(A(nRows x 256) @ W(256 x 256) + bias)
// Tile: BM=64, BN=64, BK=32, 256 threads, 4x4 microtile per thread.
// ---------------------------------------------------------------------------
template <bool SILU>
__global__ __launch_bounds__(256) void gemm_kernel(
    const float* __restrict__ A, const float* __restrict__ W,
    const float* __restrict__ bias, float* __restrict__ C, int nRows)
{
    __shared__ float As[32][64];   // [k][row]  (A stored transposed)
    __shared__ float Bs[32][64];   // [k][col]

    const int tid = threadIdx.x;
    const int tx = tid & 15;       // 0..15 -> column group
    const int ty = tid >> 4;       // 0..15 -> row group
    const int rowBase = blockIdx.x * 64;
    const int colBase = blockIdx.y * 64;

    float acc[4][4] = {};

    for (int kt = 0; kt < DIM; kt += 32) {
        // ---- load A tile (64 rows x 32 k) : 512 float4, 2 per thread ----
        #pragma unroll
        for (int e = 0; e < 2; e++) {
            int f  = tid + e * 256;
            int r  = f >> 3;             // row within tile (8 float4 per row)
            int k0 = (f & 7) * 4;
            float4 v = make_float4(0.f, 0.f, 0.f, 0.f);
            int gr = rowBase + r;
            if (gr < nRows)
                v = *(const float4*)(A + (size_t)gr * DIM + kt + k0);
            As[k0 + 0][r] = v.x;
            As[k0 + 1][r] = v.y;
            As[k0 + 2][r] = v.z;
            As[k0 + 3][r] = v.w;
        }
        // ---- load W tile (32 k x 64 cols) : 512 float4, 2 per thread ----
        #pragma unroll
        for (int e = 0; e < 2; e++) {
            int f  = tid + e * 256;
            int r  = f >> 4;             // k within tile (16 float4 per row)
            int c0 = (f & 15) * 4;
            *(float4*)&Bs[r][c0] =
                *(const float4*)(W + (size_t)(kt + r) * DIM + colBase + c0);
        }
        __syncthreads();

        #pragma unroll
        for (int k = 0; k < 32; k++) {
            float4 a4 = *(const float4*)&As[k][ty * 4];
            float4 b4 = *(const float4*)&Bs[k][tx * 4];
            float av[4] = {a4.x, a4.y, a4.z, a4.w};
            float bv[4] = {b4.x, b4.y, b4.z, b4.w};
            #pragma unroll
            for (int i = 0; i < 4; i++)
                #pragma unroll
                for (int j = 0; j < 4; j++)
                    acc[i][j] += av[i] * bv[j];
        }
        __syncthreads();
    }

    // ---- epilogue: bias (+ SiLU), float4 stores ----
    float4 bb = *(const float4*)(bias + colBase + tx * 4);
    float bv[4] = {bb.x, bb.y, bb.z, bb.w};
    #pragma unroll
    for (int i = 0; i < 4; i++) {
        int gr = rowBase + ty * 4 + i;
        if (gr < nRows) {
            float4 o;
            float v0 = acc[i][0] + bv[0];
            float v1 = acc[i][1] + bv[1];
            float v2 = acc[i][2] + bv[2];
            float v3 = acc[i][3] + bv[3];
            if (SILU) {
                v0 = silu_f(v0); v1 = silu_f(v1);
                v2 = silu_f(v2); v3 = silu_f(v3);
            }
            o.x = v0; o.y = v1; o.z = v2; o.w = v3;
            *(float4*)(C + (size_t)gr * DIM + colBase + tx * 4) = o;
        }
    }
}

// ---------------------------------------------------------------------------
// logits[i] = dot(a1[i,:], aW2[:,0]) + ab2   (one warp per node)
// ---------------------------------------------------------------------------
__global__ __launch_bounds__(256) void logits_kernel(
    const float* __restrict__ a1, const float* __restrict__ aW2,
    const float* __restrict__ ab2, float* __restrict__ logits, int nRows)
{
    int warp = (blockIdx.x * blockDim.x + threadIdx.x) >> 5;
    int lane = threadIdx.x & 31;
    if (warp >= nRows) return;
    const float* row = a1 + (size_t)warp * DIM;
    float s = 0.f;
    #pragma unroll
    for (int k = lane; k < DIM; k += 32)
        s += row[k] * __ldg(&aW2[k]);
    #pragma unroll
    for (int o = 16; o; o >>= 1)
        s += __shfl_xor_sync(0xFFFFFFFFu, s, o);
    if (lane == 0) logits[warp] = s + ab2[0];
}

// ---------------------------------------------------------------------------
// Readout: one block (256 threads) per segment. batch is sorted -> binary
// search for range. Stable softmax then weighted column-sum of x.
// ---------------------------------------------------------------------------
__device__ __forceinline__ int lower_bound_i(const int* __restrict__ a, int n, int v) {
    int lo = 0, hi = n;
    while (lo < hi) {
        int m = (lo + hi) >> 1;
        if (a[m] < v) lo = m + 1; else hi = m;
    }
    return lo;
}

__global__ __launch_bounds__(256) void readout_kernel(
    const float* __restrict__ x, const float* __restrict__ logits,
    const int* __restrict__ batch, float* __restrict__ out, int nRows)
{
    const int g = blockIdx.x;
    const int t = threadIdx.x;

    __shared__ float red[256];
    __shared__ float w[256];
    __shared__ int   srange[2];

    if (t == 0) srange[0] = lower_bound_i(batch, nRows, g);
    if (t == 1) srange[1] = lower_bound_i(batch, nRows, g + 1);
    __syncthreads();
    const int start = srange[0];
    const int end   = srange[1];

    if (start >= end) { out[(size_t)g * DIM + t] = 0.f; return; }

    // --- segment max ---
    float m = -3.402823466e38f;
    for (int i = start + t; i < end; i += 256) m = fmaxf(m, logits[i]);
    red[t] = m; __syncthreads();
    #pragma unroll
    for (int s = 128; s; s >>= 1) {
        if (t < s) red[t] = fmaxf(red[t], red[t + s]);
        __syncthreads();
    }
    m = red[0];
    __syncthreads();

    // --- exp-sum ---
    float ssum = 0.f;
    for (int i = start + t; i < end; i += 256) ssum += __expf(logits[i] - m);
    red[t] = ssum; __syncthreads();
    #pragma unroll
    for (int s = 128; s; s >>= 1) {
        if (t < s) red[t] += red[t + s];
        __syncthreads();
    }
    const float inv = 1.0f / red[0];
    __syncthreads();

    // --- weighted accumulation (thread t owns output column t) ---
    float acc = 0.f;
    for (int c0 = start; c0 < end; c0 += 256) {
        int i = c0 + t;
        __syncthreads();
        w[t] = (i < end) ? __expf(logits[i] - m) * inv : 0.f;
        __syncthreads();
        int cnt = min(256, end - c0);
        for (int j = 0; j < cnt; j++)
            acc += w[j] * x[(size_t)(c0 + j) * DIM + t];
    }
    out[(size_t)g * DIM + t] = acc;
}

// ---------------------------------------------------------------------------
// Launch
// ---------------------------------------------------------------------------
extern "C" void kernel_launch(void* const* d_in, const int* in_sizes, int n_in,
                              void* d_out, int out_size)
{
    const float* X    = (const float*)d_in[0];
    const int*   batch = (const int*)d_in[1];
    // d_in[2] = num_segments (scalar on device; G derived from out_size instead)
    const float* W1  = (const float*)d_in[3];
    const float* b1  = (const float*)d_in[4];
    const float* W2  = (const float*)d_in[5];
    const float* b2  = (const float*)d_in[6];
    const float* W3  = (const float*)d_in[7];
    const float* b3  = (const float*)d_in[8];
    const float* aW1 = (const float*)d_in[9];
    const float* ab1 = (const float*)d_in[10];
    const float* aW2 = (const float*)d_in[11];
    const float* ab2 = (const float*)d_in[12];
    float* out = (float*)d_out;

    const int N = in_sizes[0] / DIM;
    const int G = out_size / DIM;

    float *buf0, *buf1, *logits;
    cudaGetSymbolAddress((void**)&buf0, g_buf0);
    cudaGetSymbolAddress((void**)&buf1, g_buf1);
    cudaGetSymbolAddress((void**)&logits, g_logits);

    dim3 grid((N + 63) / 64, DIM / 64);

    // MLP trunk
    gemm_kernel<true ><<<grid, 256>>>(X,    W1, b1, buf0, N);   // h1
    gemm_kernel<true ><<<grid, 256>>>(buf0, W2, b2, buf1, N);   // h2
    gemm_kernel<false><<<grid, 256>>>(buf1, W3, b3, buf0, N);   // x  -> buf0
    // attention branch
    gemm_kernel<true ><<<grid, 256>>>(X,  aW1, ab1, buf1, N);   // a1 -> buf1
    logits_kernel<<<(N + 7) / 8, 256>>>(buf1, aW2, ab2, logits, N);
    // softmax readout
    readout_kernel<<<G, 256>>>(buf0, logits, batch, out, N);
}

// round 3
// speedup vs baseline: 2.4467x; 2.4467x over previous
#include <cuda_runtime.h>
#include <cuda_bf16.h>
#include <cstdint>
#include <cstddef>

// ===========================================================================
// InvariantReadout — bf16-split mma.sync (HMMA) GEMM pipeline
//   h1 = silu(X@W1+b1); h2 = silu(h1@W2+b2); x = h2@W3+b3
//   logits = silu(X@aW1+ab1)@aW2 + ab2 ; per-segment softmax; weighted sum
// fp32 operands split into bf16 hi/lo; D = Ahi*Bhi + Ahi*Blo + Alo*Bhi
// accumulated fp32 (error ~2^-16). tcgen05 unavailable at this PTX target;
// mma.sync m16n8k16 is the fastest admissible MMA path.
// ===========================================================================

#define NMAX 200000
#define DIM  256
#define BM   128
#define BN   128
#define BKT  64            // bf16 k-elems per tile (128 B rows)
#define KTILES (DIM / BKT) // 4
#define MAT_BYTES (128 * 128)          // one operand tile: 128 rows x 128B
#define STAGE_BYTES (4 * MAT_BYTES)    // Ahi, Alo, Bhi, Blo = 64KB
#define DYN_SMEM (2 * STAGE_BYTES)     // 128KB

// ---------------- scratch (__device__ globals: allocation-free rule) -------
__device__ __nv_bfloat16 g_Xhi[(size_t)NMAX * DIM];
__device__ __nv_bfloat16 g_Xlo[(size_t)NMAX * DIM];
__device__ __nv_bfloat16 g_Ahi[(size_t)NMAX * DIM];
__device__ __nv_bfloat16 g_Alo[(size_t)NMAX * DIM];
__device__ __nv_bfloat16 g_Bhi[(size_t)NMAX * DIM];
__device__ __nv_bfloat16 g_Blo[(size_t)NMAX * DIM];
__device__ float         g_f[(size_t)NMAX * DIM];   // fp32: a1, then x
__device__ float         g_logits[NMAX];
__device__ __nv_bfloat16 g_Wt[8][DIM * DIM];        // 4 weights x {hi,lo}, n-major

// ---------------- helpers ---------------------------------------------------
__device__ __forceinline__ uint32_t smem_u32(const void* p) {
    uint32_t a;
    asm("{ .reg .u64 t; cvta.to.shared.u64 t, %1; cvt.u32.u64 %0, t; }" : "=r"(a) : "l"(p));
    return a;
}
__device__ __forceinline__ void cp16(uint32_t dst, const void* src) {
    asm volatile("cp.async.cg.shared.global [%0], [%1], 16;" :: "r"(dst), "l"(src) : "memory");
}
__device__ __forceinline__ void cp_commit() {
    asm volatile("cp.async.commit_group;" ::: "memory");
}
template <int NW>
__device__ __forceinline__ void cp_wait() {
    asm volatile("cp.async.wait_group %0;" :: "n"(NW) : "memory");
}
__device__ __forceinline__ void ldsm4(uint32_t* r, uint32_t addr) {
    asm volatile("ldmatrix.sync.aligned.m8n8.x4.shared.b16 {%0,%1,%2,%3}, [%4];"
                 : "=r"(r[0]), "=r"(r[1]), "=r"(r[2]), "=r"(r[3]) : "r"(addr));
}
__device__ __forceinline__ void mma16816(float* d, const uint32_t* a, const uint32_t* b) {
    asm volatile(
        "mma.sync.aligned.m16n8k16.row.col.f32.bf16.bf16.f32 "
        "{%0,%1,%2,%3}, {%4,%5,%6,%7}, {%8,%9}, {%0,%1,%2,%3};"
        : "+f"(d[0]), "+f"(d[1]), "+f"(d[2]), "+f"(d[3])
        : "r"(a[0]), "r"(a[1]), "r"(a[2]), "r"(a[3]), "r"(b[0]), "r"(b[1]));
}
__device__ __forceinline__ float silu_f(float x) { return x / (1.0f + __expf(-x)); }
__device__ __forceinline__ void split1(float v, uint16_t& h, uint16_t& l) {
    __nv_bfloat16 hb = __float2bfloat16(v);
    float hf = __bfloat162float(hb);
    __nv_bfloat16 lb = __float2bfloat16(v - hf);
    h = __bfloat16_as_ushort(hb);
    l = __bfloat16_as_ushort(lb);
}

// ---------------- prep kernels ---------------------------------------------
__global__ __launch_bounds__(256) void xsplit_kernel(
    const float4* __restrict__ X, uint2* __restrict__ hi, uint2* __restrict__ lo, int n4)
{
    int i = blockIdx.x * 256 + threadIdx.x;
    if (i >= n4) return;
    float4 v = X[i];
    uint16_t h0,l0,h1,l1,h2,l2,h3,l3;
    split1(v.x,h0,l0); split1(v.y,h1,l1); split1(v.z,h2,l2); split1(v.w,h3,l3);
    hi[i] = make_uint2((uint32_t)h0 | ((uint32_t)h1<<16), (uint32_t)h2 | ((uint32_t)h3<<16));
    lo[i] = make_uint2((uint32_t)l0 | ((uint32_t)l1<<16), (uint32_t)l2 | ((uint32_t)l3<<16));
}

// transpose + split W[k][n] -> hi/lo[n][k]  (n-major == col-major B)
__global__ __launch_bounds__(256) void wsplit_kernel(
    const float* __restrict__ W, __nv_bfloat16* __restrict__ hi, __nv_bfloat16* __restrict__ lo)
{
    int n = blockIdx.x, k = threadIdx.x;
    float v = W[k * DIM + n];
    uint16_t h, l; split1(v, h, l);
    hi[n * DIM + k] = __ushort_as_bfloat16(h);
    lo[n * DIM + k] = __ushort_as_bfloat16(l);
}

// ---------------- mma.sync GEMM ---------------------------------------------
// C(nRows x 256) = act(A @ W + bias); A as (Ahi,Alo) row-major [m][k],
// W as (Bhi,Blo) n-major [n][k] (= col-major B). SPLIT -> bf16 hi/lo out.
template <bool SILU, bool SPLIT>
__global__ __launch_bounds__(256) void gemm_mma(
    const __nv_bfloat16* __restrict__ Ahi, const __nv_bfloat16* __restrict__ Alo,
    const __nv_bfloat16* __restrict__ Bhi, const __nv_bfloat16* __restrict__ Blo,
    const float* __restrict__ bias,
    float* __restrict__ Cf, __nv_bfloat16* __restrict__ Chi, __nv_bfloat16* __restrict__ Clo,
    int nRows)
{
    extern __shared__ char sm[];
    __shared__ float s_bias[BN];

    const int tid  = threadIdx.x;
    const int wid  = tid >> 5;
    const int lane = tid & 31;
    const int warp_m = wid >> 1;     // 0..3 -> 32-row slab
    const int warp_n = wid & 1;      // 0..1 -> 64-col slab
    const int rowBase = blockIdx.x * BM;
    const int colBase = blockIdx.y * BN;

    if (tid < BN) s_bias[tid] = bias[colBase + tid];

    const uint32_t smb = smem_u32(sm);

    // ---- async stage loader: A/B hi+lo, 128 rows x 8 chunks(16B), swizzled
    auto load_stage = [&](int s, int kt) {
        char* st = sm + s * STAGE_BYTES;
        const int ke = kt * BKT;     // k element offset
        #pragma unroll
        for (int i = 0; i < 4; i++) {
            int f = tid + i * 256;
            int r = f >> 3, c = f & 7;
            uint32_t off = (uint32_t)(r * 128 + ((c ^ (r & 7)) << 4));
            uint32_t d  = smem_u32(st) + off;
            // A rows (clamped)
            int gr = rowBase + r; if (gr >= nRows) gr = nRows - 1;
            size_t ga = (size_t)gr * DIM + ke + c * 8;
            cp16(d,                 Ahi + ga);
            cp16(d + MAT_BYTES,     Alo + ga);
            // B rows (n always < 256)
            size_t gb = (size_t)(colBase + r) * DIM + ke + c * 8;
            cp16(d + 2 * MAT_BYTES, Bhi + gb);
            cp16(d + 3 * MAT_BYTES, Blo + gb);
        }
        cp_commit();
    };

    float acc[2][8][4];
    #pragma unroll
    for (int mt = 0; mt < 2; mt++)
        #pragma unroll
        for (int j = 0; j < 8; j++)
            #pragma unroll
            for (int q = 0; q < 4; q++) acc[mt][j][q] = 0.f;

    // per-lane ldmatrix row geometry
    const int rrA = (lane & 7) + ((lane >> 3) & 1) * 8;  // row within 16-tile
    const int khA = lane >> 4;                           // k8 half
    const int rrB = (lane & 7) + (lane >> 4) * 8;
    const int khB = (lane >> 3) & 1;

    load_stage(0, 0);

    for (int kt = 0; kt < KTILES; kt++) {
        if (kt > 0) __syncthreads();           // stage buffer reuse guard
        if (kt + 1 < KTILES) load_stage((kt + 1) & 1, kt + 1);
        else cp_commit();
        cp_wait<1>();
        __syncthreads();

        const uint32_t base = smb + (kt & 1) * STAGE_BYTES;

        #pragma unroll
        for (int ks = 0; ks < 4; ks++) {       // 4 x k16 steps
            uint32_t ah[2][4], al[2][4], bh[4][4], bl[4][4];
            #pragma unroll
            for (int mt = 0; mt < 2; mt++) {
                int row = warp_m * 32 + mt * 16 + rrA;
                uint32_t a = base + row * 128 + (((ks * 2 + khA) ^ (row & 7)) << 4);
                ldsm4(ah[mt], a);
                ldsm4(al[mt], a + MAT_BYTES);
            }
            #pragma unroll
            for (int nt = 0; nt < 4; nt++) {
                int row = warp_n * 64 + nt * 16 + rrB;
                uint32_t a = base + 2 * MAT_BYTES + row * 128
                           + (((ks * 2 + khB) ^ (row & 7)) << 4);
                ldsm4(bh[nt], a);
                ldsm4(bl[nt], a + MAT_BYTES);
            }
            #pragma unroll
            for (int mt = 0; mt < 2; mt++)
                #pragma unroll
                for (int nt = 0; nt < 4; nt++)
                    #pragma unroll
                    for (int h = 0; h < 2; h++) {
                        float* d = acc[mt][nt * 2 + h];
                        mma16816(d, ah[mt], &bh[nt][h * 2]);   // hi*hi
                        mma16816(d, ah[mt], &bl[nt][h * 2]);   // hi*lo
                        mma16816(d, al[mt], &bh[nt][h * 2]);   // lo*hi
                    }
        }
    }

    // ---- epilogue: lane owns rows (g, g+8), col pair per n8 tile ----
    const int g  = lane >> 2;
    const int cp = (lane & 3) * 2;
    #pragma unroll
    for (int mt = 0; mt < 2; mt++) {
        int row0 = rowBase + warp_m * 32 + mt * 16 + g;
        #pragma unroll
        for (int j = 0; j < 8; j++) {
            int lc = warp_n * 64 + j * 8 + cp;
            float bz0 = s_bias[lc], bz1 = s_bias[lc + 1];
            #pragma unroll
            for (int hrow = 0; hrow < 2; hrow++) {
                int row = row0 + hrow * 8;
                if (row >= nRows) continue;
                float v0 = acc[mt][j][hrow * 2]     + bz0;
                float v1 = acc[mt][j][hrow * 2 + 1] + bz1;
                if (SILU) { v0 = silu_f(v0); v1 = silu_f(v1); }
                size_t o = (size_t)row * DIM + colBase + lc;
                if (SPLIT) {
                    uint16_t h0, l0, h1, l1;
                    split1(v0, h0, l0); split1(v1, h1, l1);
                    *(uint32_t*)(Chi + o) = (uint32_t)h0 | ((uint32_t)h1 << 16);
                    *(uint32_t*)(Clo + o) = (uint32_t)l0 | ((uint32_t)l1 << 16);
                } else {
                    *(float2*)(Cf + o) = make_float2(v0, v1);
                }
            }
        }
    }
}

// ---------------- logits: dot(a1[i,:], aW2) + ab2 (warp per node) ----------
__global__ __launch_bounds__(256) void logits_kernel(
    const float* __restrict__ a1, const float* __restrict__ aW2,
    const float* __restrict__ ab2, float* __restrict__ logits, int nRows)
{
    int warp = (blockIdx.x * blockDim.x + threadIdx.x) >> 5;
    int lane = threadIdx.x & 31;
    if (warp >= nRows) return;
    const float* r = a1 + (size_t)warp * DIM;
    float s = 0.f;
    #pragma unroll
    for (int k = lane; k < DIM; k += 32) s += r[k] * __ldg(&aW2[k]);
    #pragma unroll
    for (int o = 16; o; o >>= 1) s += __shfl_xor_sync(0xFFFFFFFFu, s, o);
    if (lane == 0) logits[warp] = s + ab2[0];
}

// ---------------- segment softmax readout ----------------------------------
__device__ __forceinline__ int lower_bound_i(const int* __restrict__ a, int n, int v) {
    int lo = 0, hi = n;
    while (lo < hi) { int m = (lo + hi) >> 1; if (a[m] < v) lo = m + 1; else hi = m; }
    return lo;
}

__global__ __launch_bounds__(256) void readout_kernel(
    const float* __restrict__ x, const float* __restrict__ logits,
    const int* __restrict__ batch, float* __restrict__ out, int nRows)
{
    const int g = blockIdx.x, t = threadIdx.x;
    __shared__ float red[256];
    __shared__ float w[256];
    __shared__ int   srange[2];

    if (t == 0) srange[0] = lower_bound_i(batch, nRows, g);
    if (t == 1) srange[1] = lower_bound_i(batch, nRows, g + 1);
    __syncthreads();
    const int start = srange[0], end = srange[1];
    if (start >= end) { out[(size_t)g * DIM + t] = 0.f; return; }

    float m = -3.402823466e38f;
    for (int i = start + t; i < end; i += 256) m = fmaxf(m, logits[i]);
    red[t] = m; __syncthreads();
    #pragma unroll
    for (int s = 128; s; s >>= 1) { if (t < s) red[t] = fmaxf(red[t], red[t+s]); __syncthreads(); }
    m = red[0]; __syncthreads();

    float ssum = 0.f;
    for (int i = start + t; i < end; i += 256) ssum += __expf(logits[i] - m);
    red[t] = ssum; __syncthreads();
    #pragma unroll
    for (int s = 128; s; s >>= 1) { if (t < s) red[t] += red[t+s]; __syncthreads(); }
    const float inv = 1.0f / red[0];
    __syncthreads();

    float acc = 0.f;
    for (int c0 = start; c0 < end; c0 += 256) {
        int i = c0 + t;
        __syncthreads();
        w[t] = (i < end) ? __expf(logits[i] - m) * inv : 0.f;
        __syncthreads();
        int cnt = min(256, end - c0);
        for (int j = 0; j < cnt; j++) acc += w[j] * x[(size_t)(c0 + j) * DIM + t];
    }
    out[(size_t)g * DIM + t] = acc;
}

// ---------------- launch ----------------------------------------------------
extern "C" void kernel_launch(void* const* d_in, const int* in_sizes, int n_in,
                              void* d_out, int out_size)
{
    const float* X     = (const float*)d_in[0];
    const int*   batch = (const int*)d_in[1];
    const float* W1  = (const float*)d_in[3];
    const float* b1  = (const float*)d_in[4];
    const float* W2  = (const float*)d_in[5];
    const float* b2  = (const float*)d_in[6];
    const float* W3  = (const float*)d_in[7];
    const float* b3  = (const float*)d_in[8];
    const float* aW1 = (const float*)d_in[9];
    const float* ab1 = (const float*)d_in[10];
    const float* aW2 = (const float*)d_in[11];
    const float* ab2 = (const float*)d_in[12];
    float* out = (float*)d_out;

    const int N = in_sizes[0] / DIM;
    const int G = out_size / DIM;

    __nv_bfloat16 *Xhi, *Xlo, *Ahi, *Alo, *Bhi, *Blo, *Wt;
    float *fbuf, *logits;
    cudaGetSymbolAddress((void**)&Xhi, g_Xhi);
    cudaGetSymbolAddress((void**)&Xlo, g_Xlo);
    cudaGetSymbolAddress((void**)&Ahi, g_Ahi);
    cudaGetSymbolAddress((void**)&Alo, g_Alo);
    cudaGetSymbolAddress((void**)&Bhi, g_Bhi);
    cudaGetSymbolAddress((void**)&Blo, g_Blo);
    cudaGetSymbolAddress((void**)&Wt,  g_Wt);
    cudaGetSymbolAddress((void**)&fbuf, g_f);
    cudaGetSymbolAddress((void**)&logits, g_logits);

    __nv_bfloat16* W1h = Wt + 0*DIM*DIM; __nv_bfloat16* W1l = Wt + 1*DIM*DIM;
    __nv_bfloat16* W2h = Wt + 2*DIM*DIM; __nv_bfloat16* W2l = Wt + 3*DIM*DIM;
    __nv_bfloat16* W3h = Wt + 4*DIM*DIM; __nv_bfloat16* W3l = Wt + 5*DIM*DIM;
    __nv_bfloat16* WAh = Wt + 6*DIM*DIM; __nv_bfloat16* WAl = Wt + 7*DIM*DIM;

    cudaFuncSetAttribute(gemm_mma<true,  true >, cudaFuncAttributeMaxDynamicSharedMemorySize, DYN_SMEM);
    cudaFuncSetAttribute(gemm_mma<true,  false>, cudaFuncAttributeMaxDynamicSharedMemorySize, DYN_SMEM);
    cudaFuncSetAttribute(gemm_mma<false, false>, cudaFuncAttributeMaxDynamicSharedMemorySize, DYN_SMEM);

    // prep: split X, transpose+split weights
    int n4 = N * (DIM / 4);
    xsplit_kernel<<<(n4 + 255) / 256, 256>>>((const float4*)X, (uint2*)Xhi, (uint2*)Xlo, n4);
    wsplit_kernel<<<DIM, DIM>>>(W1,  W1h, W1l);
    wsplit_kernel<<<DIM, DIM>>>(W2,  W2h, W2l);
    wsplit_kernel<<<DIM, DIM>>>(W3,  W3h, W3l);
    wsplit_kernel<<<DIM, DIM>>>(aW1, WAh, WAl);

    dim3 grid((N + BM - 1) / BM, DIM / BN);

    // attention branch first (fbuf holds a1, consumed by logits, then reused for x)
    gemm_mma<true, false><<<grid, 256, DYN_SMEM>>>(Xhi, Xlo, WAh, WAl, ab1,
                                                   fbuf, nullptr, nullptr, N);
    logits_kernel<<<(N + 7) / 8, 256>>>(fbuf, aW2, ab2, logits, N);

    // MLP trunk
    gemm_mma<true, true ><<<grid, 256, DYN_SMEM>>>(Xhi, Xlo, W1h, W1l, b1,
                                                   nullptr, Ahi, Alo, N);
    gemm_mma<true, true ><<<grid, 256, DYN_SMEM>>>(Ahi, Alo, W2h, W2l, b2,
                                                   nullptr, Bhi, Blo, N);
    gemm_mma<false, false><<<grid, 256, DYN_SMEM>>>(Bhi, Blo, W3h, W3l, b3,
                                                    fbuf, nullptr, nullptr, N);

    // softmax readout
    readout_kernel<<<G, 256>>>(fbuf, logits, batch, out, N);
}